// round 12
// baseline (speedup 1.0000x reference)
#include <cuda_runtime.h>

// SmartDoorClassifierv1 — fused CNN (LIF collapses: alpha = exp(-200) == 0 in fp32).
// Round 11: R10 retry with alignment fix. Stage-2 patch rows load as 3x float2
// (base is only 8B-aligned when e=1: (2py+1)*34 % 4 == 2 — float4 trapped).
// Keeps: __launch_bounds__(256,4), stage-2 e-split, stage-1 unroll-1, halo fill.

#define THREADS 256

// dynamic smem layout (float indices)
//  p1p : 8 x 34 x 34 = 9248   (stage-1 pooled, 1-halo)
//  p2p : 8 x 18 x 18 = 2592   (stage-2 pooled, 1-halo)
//  p3  : 512                  (flatten order)
//  sw1 : 64, sw2: 576, sw3: 576, red: 16
#define OFF_P1   0
#define OFF_P2   9248
#define OFF_P3   11840
#define OFF_W1   12352
#define OFF_W2   (OFF_W1 + 64)
#define OFF_W3   (OFF_W2 + 576)
#define OFF_RED  (OFF_W3 + 576)
#define SMEM_FLOATS (OFF_RED + 16)

__global__ __launch_bounds__(THREADS, 4)
void snn_fused_kernel(const float* __restrict__ x,
                      const float* __restrict__ w1,
                      const float* __restrict__ w2,
                      const float* __restrict__ w3,
                      const float* __restrict__ wfc,
                      float* __restrict__ out)
{
    extern __shared__ float smem[];
    float* p1p = smem + OFF_P1;
    float* p2p = smem + OFF_P2;
    float* p3  = smem + OFF_P3;
    float* sw1 = smem + OFF_W1;
    float* sw2 = smem + OFF_W2;
    float* sw3 = smem + OFF_W3;
    float* red = smem + OFF_RED;

    const int tid = threadIdx.x;
    const int n   = blockIdx.x;

    // ---- init: weights + HALO-ONLY zero fill of padded planes ----
    if (tid < 64) sw1[tid] = w1[tid];
    for (int i = tid; i < 576; i += THREADS) {
        sw2[i] = w2[i];
        sw3[i] = w3[i];
    }
    for (int i = tid; i < 8 * 34; i += THREADS) {
        int ic = i / 34, c = i % 34;
        p1p[ic * 1156 + c] = 0.f;
        p1p[ic * 1156 + 33 * 34 + c] = 0.f;
    }
    for (int i = tid; i < 8 * 32; i += THREADS) {
        int ic = i / 32, r = (i % 32) + 1;
        p1p[ic * 1156 + r * 34] = 0.f;
        p1p[ic * 1156 + r * 34 + 33] = 0.f;
    }
    for (int i = tid; i < 8 * 18; i += THREADS) {
        int ic = i / 18, c = i % 18;
        p2p[ic * 324 + c] = 0.f;
        p2p[ic * 324 + 17 * 18 + c] = 0.f;
    }
    for (int i = tid; i < 8 * 16; i += THREADS) {
        int ic = i / 16, r = (i % 16) + 1;
        p2p[ic * 324 + r * 18] = 0.f;
        p2p[ic * 324 + r * 18 + 17] = 0.f;
    }
    __syncthreads();

    // ================= Stage 1: conv1(2x2,s2) + floor(relu) + pool2 =========
    // Row-pair form; it-loop unroll 1 (prevents cross-iteration LDG batching
    // that blew register pressure in earlier rounds).
    const float* xb = x + (size_t)n * (2 * 128 * 128);
    #pragma unroll 1
    for (int it = 0; it < 4; it++) {
        int pos = tid + it * THREADS;          // 0..1023
        int py = pos >> 5, px = pos & 31;
        const float* src0 = xb + (4 * py) * 128 + 4 * px;   // ch0
        const float* src1 = src0 + 16384;                   // ch1
        float m[8];
        #pragma unroll
        for (int oc = 0; oc < 8; oc++) m[oc] = 0.f;

        #pragma unroll
        for (int dy = 0; dy < 2; dy++) {
            float4 r0a = *reinterpret_cast<const float4*>(src0 + (2*dy)   * 128);
            float4 r0b = *reinterpret_cast<const float4*>(src0 + (2*dy+1) * 128);
            float4 r1a = *reinterpret_cast<const float4*>(src1 + (2*dy)   * 128);
            float4 r1b = *reinterpret_cast<const float4*>(src1 + (2*dy+1) * 128);
            #pragma unroll
            for (int oc = 0; oc < 8; oc++) {
                const float* w = &sw1[oc * 8];
                float a0, a1;
                a0 = r0a.x * w[0];                 a1 = r0a.z * w[0];
                a0 = fmaf(r0a.y, w[1], a0);        a1 = fmaf(r0a.w, w[1], a1);
                a0 = fmaf(r0b.x, w[2], a0);        a1 = fmaf(r0b.z, w[2], a1);
                a0 = fmaf(r0b.y, w[3], a0);        a1 = fmaf(r0b.w, w[3], a1);
                a0 = fmaf(r1a.x, w[4], a0);        a1 = fmaf(r1a.z, w[4], a1);
                a0 = fmaf(r1a.y, w[5], a0);        a1 = fmaf(r1a.w, w[5], a1);
                a0 = fmaf(r1b.x, w[6], a0);        a1 = fmaf(r1b.z, w[6], a1);
                a0 = fmaf(r1b.y, w[7], a0);        a1 = fmaf(r1b.w, w[7], a1);
                m[oc] = fmaxf(m[oc], fmaxf(floorf(fmaxf(a0, 0.f)),
                                           floorf(fmaxf(a1, 0.f))));
            }
        }
        #pragma unroll
        for (int oc = 0; oc < 8; oc++)
            p1p[oc * 1156 + (py + 1) * 34 + (px + 1)] = m[oc];
    }
    __syncthreads();

    // ================= Stage 2: conv2(3x3,p1) + floor(relu) + pool2 =========
    // Thread = 4 oc x 2 adjacent pooled positions, split over output rows e.
    // Per pass: acc[4][2][2] (16 regs) + patch[3][6] (18 regs).
    // Patch rows: 3x float2 (bases are 8B-aligned for both e parities).
    {
        int pp  = tid >> 1;          // 0..127 position pair
        int ocg = tid & 1;           // oc base = ocg*4
        int py  = pp >> 3;           // 0..15
        int pxp = pp & 7;            // pooled px = 2*pxp + p

        float m[4][2];
        #pragma unroll
        for (int o = 0; o < 4; o++) { m[o][0] = 0.f; m[o][1] = 0.f; }

        #pragma unroll 1
        for (int e = 0; e < 2; e++) {
            float acc[4][2][2];      // [o][p][dx]
            #pragma unroll
            for (int o = 0; o < 4; o++)
                #pragma unroll
                for (int p = 0; p < 2; p++) {
                    acc[o][p][0] = 0.f; acc[o][p][1] = 0.f;
                }

            #pragma unroll 1
            for (int ic = 0; ic < 8; ic++) {
                const float* base = p1p + ic * 1156 + (2 * py + e) * 34 + 4 * pxp;
                float patch[3][6];
                #pragma unroll
                for (int r = 0; r < 3; r++) {
                    float2 a = *reinterpret_cast<const float2*>(base + r * 34);
                    float2 b = *reinterpret_cast<const float2*>(base + r * 34 + 2);
                    float2 c = *reinterpret_cast<const float2*>(base + r * 34 + 4);
                    patch[r][0] = a.x; patch[r][1] = a.y;
                    patch[r][2] = b.x; patch[r][3] = b.y;
                    patch[r][4] = c.x; patch[r][5] = c.y;
                }
                #pragma unroll
                for (int o = 0; o < 4; o++) {
                    const float* wp = &sw2[((ocg * 4 + o) * 8 + ic) * 9];
                    #pragma unroll
                    for (int p = 0; p < 2; p++) {
                        #pragma unroll
                        for (int d = 0; d < 2; d++) {
                            float a = acc[o][p][d];
                            #pragma unroll
                            for (int ky = 0; ky < 3; ky++)
                                #pragma unroll
                                for (int kx = 0; kx < 3; kx++)
                                    a = fmaf(patch[ky][2*p + d + kx],
                                             wp[ky * 3 + kx], a);
                            acc[o][p][d] = a;
                        }
                    }
                }
            }
            #pragma unroll
            for (int o = 0; o < 4; o++)
                #pragma unroll
                for (int p = 0; p < 2; p++) {
                    float v = fmaxf(floorf(fmaxf(acc[o][p][0], 0.f)),
                                    floorf(fmaxf(acc[o][p][1], 0.f)));
                    m[o][p] = fmaxf(m[o][p], v);
                }
        }
        #pragma unroll
        for (int o = 0; o < 4; o++)
            #pragma unroll
            for (int p = 0; p < 2; p++)
                p2p[(ocg * 4 + o) * 324 + (py + 1) * 18 + (2 * pxp + p + 1)]
                    = m[o][p];
    }
    __syncthreads();

    // ================= Stage 3: conv3(3x3,p2) + floor(relu) + pool2 =========
    // 64 pooled positions; 4 threads/pos, 2 out-channels each. ic not unrolled.
    {
        int pos = tid >> 2;                // 0..63
        int ocg = tid & 3;
        int py = pos >> 3, px = pos & 7;
        float acc[2][2][2];
        #pragma unroll
        for (int j = 0; j < 2; j++)
            #pragma unroll
            for (int a = 0; a < 2; a++)
                #pragma unroll
                for (int b = 0; b < 2; b++) acc[j][a][b] = 0.f;

        #pragma unroll 1
        for (int ic = 0; ic < 8; ic++) {
            const float* base = p2p + ic * 324 + (2 * py) * 18 + 2 * px;
            float patch[4][4];
            #pragma unroll
            for (int r = 0; r < 4; r++) {
                float2 a = *reinterpret_cast<const float2*>(base + r * 18);
                float2 b = *reinterpret_cast<const float2*>(base + r * 18 + 2);
                patch[r][0] = a.x; patch[r][1] = a.y;
                patch[r][2] = b.x; patch[r][3] = b.y;
            }
            #pragma unroll
            for (int j = 0; j < 2; j++) {
                const float* w = &sw3[((ocg * 2 + j) * 8 + ic) * 9];
                #pragma unroll
                for (int dy = 0; dy < 2; dy++) {
                    #pragma unroll
                    for (int dx = 0; dx < 2; dx++) {
                        float a = acc[j][dy][dx];
                        #pragma unroll
                        for (int ky = 0; ky < 3; ky++)
                            #pragma unroll
                            for (int kx = 0; kx < 3; kx++)
                                a = fmaf(patch[dy+ky][dx+kx], w[ky*3+kx], a);
                        acc[j][dy][dx] = a;
                    }
                }
            }
        }
        #pragma unroll
        for (int j = 0; j < 2; j++) {
            int oc = ocg * 2 + j;
            float m = 0.f;
            #pragma unroll
            for (int dy = 0; dy < 2; dy++)
                #pragma unroll
                for (int dx = 0; dx < 2; dx++)
                    m = fmaxf(m, floorf(fmaxf(acc[j][dy][dx], 0.f)));
            p3[oc * 64 + py * 8 + px] = m;     // flatten order c*64 + y*8 + x
        }
    }
    __syncthreads();

    // ================= Stage 4: fc (512 -> 2) ===============================
    {
        float a0 = 0.f, a1 = 0.f;
        #pragma unroll
        for (int k = 0; k < 2; k++) {
            int j = tid + k * THREADS;         // 0..511
            float v = p3[j];
            a0 = fmaf(v, wfc[j],       a0);
            a1 = fmaf(v, wfc[512 + j], a1);
        }
        #pragma unroll
        for (int off = 16; off > 0; off >>= 1) {
            a0 += __shfl_down_sync(0xffffffffu, a0, off);
            a1 += __shfl_down_sync(0xffffffffu, a1, off);
        }
        if ((tid & 31) == 0) {
            red[tid >> 5]       = a0;
            red[8 + (tid >> 5)] = a1;
        }
        __syncthreads();
        if (tid == 0) {
            float s0 = 0.f, s1 = 0.f;
            #pragma unroll
            for (int i = 0; i < 8; i++) { s0 += red[i]; s1 += red[8 + i]; }
            out[n * 2 + 0] = s0;
            out[n * 2 + 1] = s1;
        }
    }
}

extern "C" void kernel_launch(void* const* d_in, const int* in_sizes, int n_in,
                              void* d_out, int out_size)
{
    const float* x   = (const float*)d_in[0];
    const float* w1  = (const float*)d_in[1];
    const float* w2  = (const float*)d_in[2];
    const float* w3  = (const float*)d_in[3];
    const float* wfc = (const float*)d_in[4];
    int nsamples = in_sizes[0] / (2 * 128 * 128);   // 1024

    size_t smem_bytes = SMEM_FLOATS * sizeof(float);  // ~54.3 KB
    cudaFuncSetAttribute(snn_fused_kernel,
                         cudaFuncAttributeMaxDynamicSharedMemorySize,
                         (int)smem_bytes);
    snn_fused_kernel<<<nsamples, THREADS, smem_bytes>>>(x, w1, w2, w3, wfc,
                                                        (float*)d_out);
}

// round 13
// speedup vs baseline: 1.8141x; 1.8141x over previous
#include <cuda_runtime.h>

// SmartDoorClassifierv1 — fused CNN (LIF collapses: alpha = exp(-200) == 0 in fp32).
// Round 12: LDS-op reduction at (256,3). Vectorized + bank-padded weight
// layouts (LDS.128), p1p row stride 36 -> float4 patch rows, stage-1 inputs
// loaded once per it with per-oc weight regs. R11 showed 4 CTAs/SM saturates
// L1 — stay at 3 and cut LDS instruction count ~2.4x instead.

#define THREADS 256

// dynamic smem layout (float indices)
//  p1p  : 8 x 34 x 36 = 9792  (stage-1 pooled, 1-halo, row stride 36 for 16B align)
//  p2p  : 8 x 18 x 18 = 2592  (stage-2 pooled, 1-halo)
//  p3   : 512                 (flatten order)
//  sw1  : 64                  (oc-major, float4-able)
//  sw2p : 772   (2 ocg blocks, block stride 388, per-(o,ic) stride 12)
//  sw3p : 800   (8 oc blocks, oc stride 100, per-ic stride 12)
//  red  : 16
#define OFF_P1   0
#define OFF_P2   9792
#define OFF_P3   12384
#define OFF_W1   12896
#define OFF_W2   12960
#define OFF_W3   13732
#define OFF_RED  14532
#define SMEM_FLOATS (OFF_RED + 16)

#define P1_RS   36
#define P1_PL   (34 * P1_RS)      // 1224 floats per channel plane

__global__ __launch_bounds__(THREADS, 3)
void snn_fused_kernel(const float* __restrict__ x,
                      const float* __restrict__ w1,
                      const float* __restrict__ w2,
                      const float* __restrict__ w3,
                      const float* __restrict__ wfc,
                      float* __restrict__ out)
{
    extern __shared__ float smem[];
    float* p1p  = smem + OFF_P1;
    float* p2p  = smem + OFF_P2;
    float* p3   = smem + OFF_P3;
    float* sw1  = smem + OFF_W1;
    float* sw2p = smem + OFF_W2;
    float* sw3p = smem + OFF_W3;
    float* red  = smem + OFF_RED;

    const int tid = threadIdx.x;
    const int n   = blockIdx.x;

    // ---- init: weights (padded layouts) + halo-only zero fill ----
    if (tid < 64) sw1[tid] = w1[tid];
    for (int i = tid; i < 576; i += THREADS) {
        int oc = i / 72, rem = i % 72, ic = rem / 9, k = rem % 9;
        // sw2p: ocg block stride 388 (bank offset 4), (o,ic) stride 12 (16B)
        sw2p[(oc >> 2) * 388 + ((oc & 3) * 8 + ic) * 12 + k] = w2[i];
        // sw3p: oc stride 100 (bank offset 4 per oc pair), ic stride 12
        sw3p[oc * 100 + ic * 12 + k] = w3[i];
    }
    for (int i = tid; i < 8 * 34; i += THREADS) {
        int ic = i / 34, c = i % 34;
        p1p[ic * P1_PL + c] = 0.f;
        p1p[ic * P1_PL + 33 * P1_RS + c] = 0.f;
    }
    for (int i = tid; i < 8 * 32; i += THREADS) {
        int ic = i / 32, r = (i % 32) + 1;
        p1p[ic * P1_PL + r * P1_RS] = 0.f;
        p1p[ic * P1_PL + r * P1_RS + 33] = 0.f;
    }
    for (int i = tid; i < 8 * 18; i += THREADS) {
        int ic = i / 18, c = i % 18;
        p2p[ic * 324 + c] = 0.f;
        p2p[ic * 324 + 17 * 18 + c] = 0.f;
    }
    for (int i = tid; i < 8 * 16; i += THREADS) {
        int ic = i / 16, r = (i % 16) + 1;
        p2p[ic * 324 + r * 18] = 0.f;
        p2p[ic * 324 + r * 18 + 17] = 0.f;
    }
    __syncthreads();

    // ================= Stage 1: conv1(2x2,s2) + floor(relu) + pool2 =========
    // Inputs for the whole 4x4 patch loaded once per it (8x LDG.128); weights
    // per oc as 2x float4 broadcast LDS. it-loop unroll 1 bounds live range.
    const float* xb = x + (size_t)n * (2 * 128 * 128);
    #pragma unroll 1
    for (int it = 0; it < 4; it++) {
        int pos = tid + it * THREADS;          // 0..1023
        int py = pos >> 5, px = pos & 31;
        const float* src0 = xb + (4 * py) * 128 + 4 * px;   // ch0
        const float* src1 = src0 + 16384;                   // ch1
        float4 c0r0 = *reinterpret_cast<const float4*>(src0);
        float4 c0r1 = *reinterpret_cast<const float4*>(src0 + 128);
        float4 c0r2 = *reinterpret_cast<const float4*>(src0 + 256);
        float4 c0r3 = *reinterpret_cast<const float4*>(src0 + 384);
        float4 c1r0 = *reinterpret_cast<const float4*>(src1);
        float4 c1r1 = *reinterpret_cast<const float4*>(src1 + 128);
        float4 c1r2 = *reinterpret_cast<const float4*>(src1 + 256);
        float4 c1r3 = *reinterpret_cast<const float4*>(src1 + 384);

        float* dst = p1p + (py + 1) * P1_RS + (px + 1);
        #pragma unroll
        for (int oc = 0; oc < 8; oc++) {
            const float* wb = sw1 + oc * 8;
            float4 wA = *reinterpret_cast<const float4*>(wb);      // ch0 2x2
            float4 wB = *reinterpret_cast<const float4*>(wb + 4);  // ch1 2x2
            // conv outputs (dy,dx) on the 4x4 patch, then floor/relu/max
            float v00, v01, v10, v11;
            v00 = c0r0.x * wA.x;               v01 = c0r0.z * wA.x;
            v00 = fmaf(c0r0.y, wA.y, v00);     v01 = fmaf(c0r0.w, wA.y, v01);
            v00 = fmaf(c0r1.x, wA.z, v00);     v01 = fmaf(c0r1.z, wA.z, v01);
            v00 = fmaf(c0r1.y, wA.w, v00);     v01 = fmaf(c0r1.w, wA.w, v01);
            v00 = fmaf(c1r0.x, wB.x, v00);     v01 = fmaf(c1r0.z, wB.x, v01);
            v00 = fmaf(c1r0.y, wB.y, v00);     v01 = fmaf(c1r0.w, wB.y, v01);
            v00 = fmaf(c1r1.x, wB.z, v00);     v01 = fmaf(c1r1.z, wB.z, v01);
            v00 = fmaf(c1r1.y, wB.w, v00);     v01 = fmaf(c1r1.w, wB.w, v01);

            v10 = c0r2.x * wA.x;               v11 = c0r2.z * wA.x;
            v10 = fmaf(c0r2.y, wA.y, v10);     v11 = fmaf(c0r2.w, wA.y, v11);
            v10 = fmaf(c0r3.x, wA.z, v10);     v11 = fmaf(c0r3.z, wA.z, v11);
            v10 = fmaf(c0r3.y, wA.w, v10);     v11 = fmaf(c0r3.w, wA.w, v11);
            v10 = fmaf(c1r2.x, wB.x, v10);     v11 = fmaf(c1r2.z, wB.x, v11);
            v10 = fmaf(c1r2.y, wB.y, v10);     v11 = fmaf(c1r2.w, wB.y, v11);
            v10 = fmaf(c1r3.x, wB.z, v10);     v11 = fmaf(c1r3.z, wB.z, v11);
            v10 = fmaf(c1r3.y, wB.w, v10);     v11 = fmaf(c1r3.w, wB.w, v11);

            float m = fmaxf(fmaxf(floorf(fmaxf(v00, 0.f)),
                                  floorf(fmaxf(v01, 0.f))),
                            fmaxf(floorf(fmaxf(v10, 0.f)),
                                  floorf(fmaxf(v11, 0.f))));
            dst[oc * P1_PL] = m;
        }
    }
    __syncthreads();

    // ================= Stage 2: conv2(3x3,p1) + floor(relu) + pool2 =========
    // Thread = 4 oc x 2 adjacent pooled positions (R9 joint form, no e-split).
    // Patch rows: float4 + float2 (16B-aligned via P1_RS=36). Weights:
    // 2x LDS.128 + 1 scalar from padded sw2p, conflict-free across lane parity.
    {
        int pp  = tid >> 1;          // 0..127 position pair
        int ocg = tid & 1;           // oc base = ocg*4
        int py  = pp >> 3;           // 0..15
        int pxp = pp & 7;            // pooled px = 2*pxp + p

        float acc[4][2][2][2];       // [o][p][dy][dx]
        #pragma unroll
        for (int o = 0; o < 4; o++)
            #pragma unroll
            for (int p = 0; p < 2; p++)
                #pragma unroll
                for (int e = 0; e < 2; e++) {
                    acc[o][p][e][0] = 0.f; acc[o][p][e][1] = 0.f;
                }

        #pragma unroll 1
        for (int ic = 0; ic < 8; ic++) {
            const float* base = p1p + ic * P1_PL + (2 * py) * P1_RS + 4 * pxp;
            float patch[4][6];
            #pragma unroll
            for (int r = 0; r < 4; r++) {
                float4 a = *reinterpret_cast<const float4*>(base + r * P1_RS);
                float2 c = *reinterpret_cast<const float2*>(base + r * P1_RS + 4);
                patch[r][0] = a.x; patch[r][1] = a.y;
                patch[r][2] = a.z; patch[r][3] = a.w;
                patch[r][4] = c.x; patch[r][5] = c.y;
            }
            const float* wblk = sw2p + ocg * 388 + ic * 12;
            #pragma unroll
            for (int o = 0; o < 4; o++) {
                const float* wb = wblk + o * 96;   // (o*8+ic)*12 = o*96 + ic*12
                float4 wA = *reinterpret_cast<const float4*>(wb);
                float4 wB = *reinterpret_cast<const float4*>(wb + 4);
                float wk[9] = {wA.x, wA.y, wA.z, wA.w,
                               wB.x, wB.y, wB.z, wB.w, wb[8]};
                #pragma unroll
                for (int p = 0; p < 2; p++) {
                    #pragma unroll
                    for (int e = 0; e < 2; e++) {
                        #pragma unroll
                        for (int d = 0; d < 2; d++) {
                            float a = acc[o][p][e][d];
                            #pragma unroll
                            for (int ky = 0; ky < 3; ky++)
                                #pragma unroll
                                for (int kx = 0; kx < 3; kx++)
                                    a = fmaf(patch[e + ky][2*p + d + kx],
                                             wk[ky * 3 + kx], a);
                            acc[o][p][e][d] = a;
                        }
                    }
                }
            }
        }
        #pragma unroll
        for (int o = 0; o < 4; o++) {
            #pragma unroll
            for (int p = 0; p < 2; p++) {
                float m = 0.f;
                #pragma unroll
                for (int e = 0; e < 2; e++)
                    #pragma unroll
                    for (int d = 0; d < 2; d++)
                        m = fmaxf(m, floorf(fmaxf(acc[o][p][e][d], 0.f)));
                p2p[(ocg * 4 + o) * 324 + (py + 1) * 18 + (2 * pxp + p + 1)] = m;
            }
        }
    }
    __syncthreads();

    // ================= Stage 3: conv3(3x3,p2) + floor(relu) + pool2 =========
    // 64 pooled positions; 4 threads/pos, 2 out-channels each. Padded sw3p:
    // 4 ocg lanes hit disjoint bank quads; weights as 2x LDS.128 + scalar.
    {
        int pos = tid >> 2;                // 0..63
        int ocg = tid & 3;
        int py = pos >> 3, px = pos & 7;
        float acc[2][2][2];
        #pragma unroll
        for (int j = 0; j < 2; j++)
            #pragma unroll
            for (int a = 0; a < 2; a++)
                #pragma unroll
                for (int b = 0; b < 2; b++) acc[j][a][b] = 0.f;

        #pragma unroll 1
        for (int ic = 0; ic < 8; ic++) {
            const float* base = p2p + ic * 324 + (2 * py) * 18 + 2 * px;
            float patch[4][4];
            #pragma unroll
            for (int r = 0; r < 4; r++) {
                float2 a = *reinterpret_cast<const float2*>(base + r * 18);
                float2 b = *reinterpret_cast<const float2*>(base + r * 18 + 2);
                patch[r][0] = a.x; patch[r][1] = a.y;
                patch[r][2] = b.x; patch[r][3] = b.y;
            }
            #pragma unroll
            for (int j = 0; j < 2; j++) {
                const float* wb = sw3p + (ocg * 2 + j) * 100 + ic * 12;
                float4 wA = *reinterpret_cast<const float4*>(wb);
                float4 wB = *reinterpret_cast<const float4*>(wb + 4);
                float wk[9] = {wA.x, wA.y, wA.z, wA.w,
                               wB.x, wB.y, wB.z, wB.w, wb[8]};
                #pragma unroll
                for (int dy = 0; dy < 2; dy++) {
                    #pragma unroll
                    for (int dx = 0; dx < 2; dx++) {
                        float a = acc[j][dy][dx];
                        #pragma unroll
                        for (int ky = 0; ky < 3; ky++)
                            #pragma unroll
                            for (int kx = 0; kx < 3; kx++)
                                a = fmaf(patch[dy+ky][dx+kx], wk[ky*3+kx], a);
                        acc[j][dy][dx] = a;
                    }
                }
            }
        }
        #pragma unroll
        for (int j = 0; j < 2; j++) {
            int oc = ocg * 2 + j;
            float m = 0.f;
            #pragma unroll
            for (int dy = 0; dy < 2; dy++)
                #pragma unroll
                for (int dx = 0; dx < 2; dx++)
                    m = fmaxf(m, floorf(fmaxf(acc[j][dy][dx], 0.f)));
            p3[oc * 64 + py * 8 + px] = m;     // flatten order c*64 + y*8 + x
        }
    }
    __syncthreads();

    // ================= Stage 4: fc (512 -> 2) ===============================
    {
        float a0 = 0.f, a1 = 0.f;
        #pragma unroll
        for (int k = 0; k < 2; k++) {
            int j = tid + k * THREADS;         // 0..511
            float v = p3[j];
            a0 = fmaf(v, wfc[j],       a0);
            a1 = fmaf(v, wfc[512 + j], a1);
        }
        #pragma unroll
        for (int off = 16; off > 0; off >>= 1) {
            a0 += __shfl_down_sync(0xffffffffu, a0, off);
            a1 += __shfl_down_sync(0xffffffffu, a1, off);
        }
        if ((tid & 31) == 0) {
            red[tid >> 5]       = a0;
            red[8 + (tid >> 5)] = a1;
        }
        __syncthreads();
        if (tid == 0) {
            float s0 = 0.f, s1 = 0.f;
            #pragma unroll
            for (int i = 0; i < 8; i++) { s0 += red[i]; s1 += red[8 + i]; }
            out[n * 2 + 0] = s0;
            out[n * 2 + 1] = s1;
        }
    }
}

extern "C" void kernel_launch(void* const* d_in, const int* in_sizes, int n_in,
                              void* d_out, int out_size)
{
    const float* x   = (const float*)d_in[0];
    const float* w1  = (const float*)d_in[1];
    const float* w2  = (const float*)d_in[2];
    const float* w3  = (const float*)d_in[3];
    const float* wfc = (const float*)d_in[4];
    int nsamples = in_sizes[0] / (2 * 128 * 128);   // 1024

    size_t smem_bytes = SMEM_FLOATS * sizeof(float);  // ~56.8 KB
    cudaFuncSetAttribute(snn_fused_kernel,
                         cudaFuncAttributeMaxDynamicSharedMemorySize,
                         (int)smem_bytes);
    snn_fused_kernel<<<nsamples, THREADS, smem_bytes>>>(x, w1, w2, w3, wfc,
                                                        (float*)d_out);
}